// round 11
// baseline (speedup 1.0000x reference)
#include <cuda_runtime.h>

typedef unsigned long long u64;

#define POS_DIM 15
#define N_LAYERS 32
#define H 16
#define IN_DIM (4 + 4 * 2 * POS_DIM)   // 124
#define THREADS 256
#define ROWS 2

#define W1_N (IN_DIM * H)        // 1984
#define WS_N (N_LAYERS * H * H)  // 8192
#define BS_N (N_LAYERS * H)      // 512

// dynamic SMEM carve (floats)
#define OFF_WSD 0                      // duplicated Ws: 16384
#define OFF_W1  (OFF_WSD + 2 * WS_N)   // 16384
#define OFF_BSD (OFF_W1 + W1_N)        // 18368 (dup bs: 1024)
#define OFF_B1  (OFF_BSD + 2 * BS_N)   // 19392
#define OFF_WF  (OFF_B1 + H)           // 19408
#define OFF_BF  (OFF_WF + H)           // 19424
#define SMEM_FLOATS (OFF_BF + 4)       // pad
#define SMEM_BYTES (SMEM_FLOATS * 4)

// ---- packed f32x2 helpers ----
__device__ __forceinline__ u64 pack2(float lo, float hi) {
    u64 r; asm("mov.b64 %0, {%1, %2};" : "=l"(r) : "f"(lo), "f"(hi)); return r;
}
__device__ __forceinline__ void unpack2(u64 v, float& lo, float& hi) {
    asm("mov.b64 {%0, %1}, %2;" : "=f"(lo), "=f"(hi) : "l"(v));
}
__device__ __forceinline__ u64 fma2(u64 a, u64 b, u64 c) {
    u64 d; asm("fma.rn.f32x2 %0, %1, %2, %3;" : "=l"(d) : "l"(a), "l"(b), "l"(c)); return d;
}
__device__ __forceinline__ u64 mul2(u64 a, u64 b) {
    u64 d; asm("mul.rn.f32x2 %0, %1, %2;" : "=l"(d) : "l"(a), "l"(b)); return d;
}
__device__ __forceinline__ u64 abs2(u64 a) { return a & 0x7fffffff7fffffffULL; }

// leaky(x) = 0.6x + 0.4|x|  (exact for slope 0.2)
#define C06 0x3F19999A3F19999AULL
#define C04 0x3ECCCCCD3ECCCCCDULL

__device__ __forceinline__ u64 resleaky2(u64 t, u64 h_old) {
    return fma2(abs2(t), C04, fma2(t, C06, h_old));
}
__device__ __forceinline__ u64 leaky2(u64 t) {
    return fma2(abs2(t), C04, mul2(t, C06));
}

__global__ __launch_bounds__(THREADS, 2)
void fractal_mlp_kernel(const float* __restrict__ z,
                        const float* __restrict__ c,
                        const float* __restrict__ W1,
                        const float* __restrict__ b1,
                        const float* __restrict__ Ws,
                        const float* __restrict__ bs,
                        const float* __restrict__ Wf,
                        const float* __restrict__ bf,
                        float* __restrict__ out,
                        int B)
{
    extern __shared__ __align__(16) float smem[];
    float* sWsD = smem + OFF_WSD;   // lane-duplicated Ws: (w,w) pairs
    float* sW1  = smem + OFF_W1;    // plain W1
    float* sBsD = smem + OFF_BSD;   // lane-duplicated bs
    float* sB1  = smem + OFF_B1;
    float* sWf  = smem + OFF_WF;
    float* sBf  = smem + OFF_BF;

    const int tid = threadIdx.x;
    {   // staging: Ws/bs duplicated elementwise (dup[2i]=dup[2i+1]=w[i])
        const float2* ws2 = (const float2*)Ws;
        float4* wd4 = (float4*)sWsD;
        for (int i = tid; i < WS_N / 2; i += THREADS) {
            float2 t = ws2[i];
            wd4[i] = make_float4(t.x, t.x, t.y, t.y);
        }
        const float2* bs2 = (const float2*)bs;
        float4* bd4 = (float4*)sBsD;
        for (int i = tid; i < BS_N / 2; i += THREADS) {
            float2 t = bs2[i];
            bd4[i] = make_float4(t.x, t.x, t.y, t.y);
        }
        const float4* g = (const float4*)W1;
        float4* s = (float4*)sW1;
        for (int i = tid; i < W1_N / 4; i += THREADS) s[i] = g[i];
        if (tid < H) { sB1[tid] = b1[tid]; sWf[tid] = Wf[tid]; }
        if (tid == 0) sBf[0] = bf[0];
    }
    __syncthreads();

    const int base = blockIdx.x * (THREADS * ROWS) + tid;
    const int rowA = base;
    const int rowB = base + THREADS;
    const int rA = rowA < B ? rowA : B - 1;
    const int rB = rowB < B ? rowB : B - 1;

    const float2* z2 = reinterpret_cast<const float2*>(z);
    const float2* c2 = reinterpret_cast<const float2*>(c);
    float2 zA = z2[rA], cA = c2[rA];
    float2 zB = z2[rB], cB = c2[rB];
    float xA[4] = {zA.x, zA.y, cA.x, cA.y};
    float xB[4] = {zB.x, zB.y, cB.x, cB.y};

    // ---- First layer (j-pair packed per row, as before) ----
    u64 accA[8], accB[8];
    {
        const ulonglong2* b1v = reinterpret_cast<const ulonglong2*>(sB1);
#pragma unroll
        for (int q = 0; q < 4; q++) {
            ulonglong2 t = b1v[q];
            accA[2 * q] = t.x; accA[2 * q + 1] = t.y;
            accB[2 * q] = t.x; accB[2 * q + 1] = t.y;
        }
    }

    const ulonglong2* w1v = reinterpret_cast<const ulonglong2*>(sW1);

#define ACC2(feat, vA, vB)                                            \
    {                                                                 \
        const u64 pA = pack2((vA), (vA));                             \
        const u64 pB = pack2((vB), (vB));                             \
        const ulonglong2* r = w1v + (feat) * 4;                       \
        _Pragma("unroll")                                             \
        for (int q = 0; q < 4; q++) {                                 \
            ulonglong2 wv = r[q];                                     \
            accA[2 * q]     = fma2(pA, wv.x, accA[2 * q]);            \
            accA[2 * q + 1] = fma2(pA, wv.y, accA[2 * q + 1]);        \
            accB[2 * q]     = fma2(pB, wv.x, accB[2 * q]);            \
            accB[2 * q + 1] = fma2(pB, wv.y, accB[2 * q + 1]);        \
        }                                                             \
    }

#pragma unroll
    for (int d = 0; d < 4; d++) ACC2(d, xA[d], xB[d]);

    // positional encoding: anchored double-angle (anchors f=0,5,10; 4 doublings each)
#pragma unroll 1
    for (int d = 0; d < 4; d++) {
        const float aAv = xA[d];
        const float aBv = xB[d];
#pragma unroll
        for (int an = 0; an < 3; an++) {
            const float sc = (an == 0) ? 1.0f : ((an == 1) ? 32.0f : 1024.0f);
            float sA, cAv, sB, cBv;
            sincosf(aAv * sc, &sA, &cAv);
            sincosf(aBv * sc, &sB, &cBv);
#pragma unroll
            for (int g = 0; g < 5; g++) {
                const int f = an * 5 + g;
                ACC2(4 + f * 8 + d, sA, sB);       // sin feature
                ACC2(8 + f * 8 + d, cAv, cBv);     // cos feature
                if (g < 4) {
                    float tA = sA * cAv;
                    float nA = fmaf(cAv, cAv, -(sA * sA));
                    sA = tA + tA; cAv = nA;
                    float tB = sB * cBv;
                    float nB = fmaf(cBv, cBv, -(sB * sB));
                    sB = tB + tB; cBv = nB;
                }
            }
        }
    }

    // boundary: leaky, then repack (rowA,rowB) into lanes — ONCE
    u64 hp[H];   // hp[j] = (hA_j, hB_j)
#pragma unroll
    for (int p = 0; p < 8; p++) {
        float a0, a1, b0, b1v_;
        unpack2(leaky2(accA[p]), a0, a1);
        unpack2(leaky2(accB[p]), b0, b1v_);
        hp[2 * p]     = pack2(a0, b0);
        hp[2 * p + 1] = pack2(a1, b1v_);
    }

    // ---- 32 residual layers: pure LDS->FFMA2, zero MOVs in the loop ----
#pragma unroll 2
    for (int L = 0; L < N_LAYERS; L++) {
        const ulonglong2* wd = reinterpret_cast<const ulonglong2*>(sWsD + L * 512);
        const ulonglong2* bd = reinterpret_cast<const ulonglong2*>(sBsD + L * 32);
        u64 a[H];
#pragma unroll
        for (int q = 0; q < 8; q++) {
            ulonglong2 t = bd[q];
            a[2 * q] = t.x; a[2 * q + 1] = t.y;
        }
#pragma unroll
        for (int k = 0; k < H; k++) {
            const u64 v = hp[k];   // (hA_k, hB_k) — already packed
#pragma unroll
            for (int q = 0; q < 8; q++) {
                ulonglong2 wv = wd[k * 8 + q];   // ((w,w),(w',w')) duplicated
                a[2 * q]     = fma2(v, wv.x, a[2 * q]);
                a[2 * q + 1] = fma2(v, wv.y, a[2 * q + 1]);
            }
        }
#pragma unroll
        for (int j = 0; j < H; j++)
            hp[j] = resleaky2(a[j], hp[j]);   // stays packed
    }

    // ---- Final: out = h @ Wf + bf ----
    float oA = sBf[0], oB = sBf[0];
#pragma unroll
    for (int j = 0; j < H; j++) {
        float hAj, hBj;
        unpack2(hp[j], hAj, hBj);
        oA = fmaf(hAj, sWf[j], oA);
        oB = fmaf(hBj, sWf[j], oB);
    }
    if (rowA < B) out[rowA] = oA;
    if (rowB < B) out[rowB] = oB;
}

extern "C" void kernel_launch(void* const* d_in, const int* in_sizes, int n_in,
                              void* d_out, int out_size)
{
    const float* z  = (const float*)d_in[0];
    const float* c  = (const float*)d_in[1];
    const float* W1 = (const float*)d_in[2];
    const float* b1 = (const float*)d_in[3];
    const float* Ws = (const float*)d_in[4];
    const float* bs = (const float*)d_in[5];
    const float* Wf = (const float*)d_in[6];
    const float* bf = (const float*)d_in[7];

    const int B = in_sizes[0] / 2;   // z is (B, 2)
    const int rows_per_block = THREADS * ROWS;
    const int blocks = (B + rows_per_block - 1) / rows_per_block;

    static int smem_set = 0;
    if (!smem_set) {
        cudaFuncSetAttribute(fractal_mlp_kernel,
                             cudaFuncAttributeMaxDynamicSharedMemorySize,
                             SMEM_BYTES);
        smem_set = 1;
    }

    fractal_mlp_kernel<<<blocks, THREADS, SMEM_BYTES>>>(z, c, W1, b1, Ws, bs,
                                                        Wf, bf,
                                                        (float*)d_out, B);
}

// round 13
// speedup vs baseline: 1.1589x; 1.1589x over previous
#include <cuda_runtime.h>

typedef unsigned long long u64;

#define POS_DIM 15
#define N_LAYERS 32
#define H 16
#define IN_DIM (4 + 4 * 2 * POS_DIM)   // 124
#define THREADS 256
#define ROWS 2
#define NPAIR 62                        // 124 features / 2

#define W1T_N (NPAIR * H * 2)    // 1984
#define WST_N (N_LAYERS * H * H) // 8192 floats (transposed-paired, 256/layer)
#define BS_N (N_LAYERS * H)      // 512

// ---- packed f32x2 helpers ----
__device__ __forceinline__ u64 pack2(float lo, float hi) {
    u64 r; asm("mov.b64 %0, {%1, %2};" : "=l"(r) : "f"(lo), "f"(hi)); return r;
}
__device__ __forceinline__ void unpack2(u64 v, float& lo, float& hi) {
    asm("mov.b64 {%0, %1}, %2;" : "=f"(lo), "=f"(hi) : "l"(v));
}
__device__ __forceinline__ u64 fma2(u64 a, u64 b, u64 c) {
    u64 d; asm("fma.rn.f32x2 %0, %1, %2, %3;" : "=l"(d) : "l"(a), "l"(b), "l"(c)); return d;
}
__device__ __forceinline__ u64 mul2(u64 a, u64 b) {
    u64 d; asm("mul.rn.f32x2 %0, %1, %2;" : "=l"(d) : "l"(a), "l"(b)); return d;
}
__device__ __forceinline__ u64 add2(u64 a, u64 b) {
    u64 d; asm("add.rn.f32x2 %0, %1, %2;" : "=l"(d) : "l"(a), "l"(b)); return d;
}
__device__ __forceinline__ u64 abs2(u64 a) { return a & 0x7fffffff7fffffffULL; }
__device__ __forceinline__ u64 neg2(u64 a) { return a ^ 0x8000000080000000ULL; }

// leaky(x) = 0.6x + 0.4|x|  (exact for slope 0.2)
#define C06 0x3F19999A3F19999AULL
#define C04 0x3ECCCCCD3ECCCCCDULL

__device__ __forceinline__ u64 resleaky2(u64 t, u64 h_old) {
    return fma2(abs2(t), C04, fma2(t, C06, h_old));
}
__device__ __forceinline__ u64 leaky2(u64 t) {
    return fma2(abs2(t), C04, mul2(t, C06));
}

__global__ __launch_bounds__(THREADS, 2)
void fractal_mlp_kernel(const float* __restrict__ z,
                        const float* __restrict__ c,
                        const float* __restrict__ W1,
                        const float* __restrict__ b1,
                        const float* __restrict__ Ws,
                        const float* __restrict__ bs,
                        const float* __restrict__ Wf,
                        const float* __restrict__ bf,
                        float* __restrict__ out,
                        int B)
{
    // Transposed-paired weights: lanes carry (even-k, odd-k) partials.
    // Layout per layer: 256 floats = 8 pair-rows (m) x 16 outputs (j) x float2.
    __shared__ __align__(16) float sWsT[WST_N];  // [L][m][j] pairs (w_{2m,j}, w_{2m+1,j})
    __shared__ __align__(16) float sW1T[W1T_N];  // [m][j] pairs (W1[2m][j], W1[2m+1][j])
    __shared__ __align__(16) float sBs[BS_N];
    __shared__ __align__(16) float sB1[H];
    __shared__ __align__(16) float sWf[H];
    __shared__ float sBf;

    const int tid = threadIdx.x;
    {   // stage + transpose-pair weights (once per CTA; GMEM is L2-resident)
        float2* wsT2 = (float2*)sWsT;
        for (int i = tid; i < WST_N / 2; i += THREADS) {      // 4096 float2, L=0..31
            int L = i >> 7, rem = i & 127, m = rem >> 4, j = rem & 15;
            const float* src = Ws + L * 256 + m * 32 + j;
            wsT2[i] = make_float2(src[0], src[16]);
        }
        float2* w1T2s = (float2*)sW1T;
        for (int i = tid; i < W1T_N / 2; i += THREADS) {      // 992 float2
            int m = i >> 4, j = i & 15;
            const float* src = W1 + m * 32 + j;
            w1T2s[i] = make_float2(src[0], src[16]);
        }
        const float4* g = (const float4*)bs;
        float4* s = (float4*)sBs;
        for (int i = tid; i < BS_N / 4; i += THREADS) s[i] = g[i];
        if (tid < H) { sB1[tid] = b1[tid]; sWf[tid] = Wf[tid]; }
        if (tid == 0) sBf = bf[0];
    }
    __syncthreads();

    const int base = blockIdx.x * (THREADS * ROWS) + tid;
    const int rowA = base;
    const int rowB = base + THREADS;
    const int rA = rowA < B ? rowA : B - 1;
    const int rB = rowB < B ? rowB : B - 1;

    const float2* z2 = reinterpret_cast<const float2*>(z);
    const float2* c2 = reinterpret_cast<const float2*>(c);
    float2 zA = z2[rA], cA = c2[rA];
    float2 zB = z2[rB], cB = c2[rB];
    float xA[4] = {zA.x, zA.y, cA.x, cA.y};
    float xB[4] = {zB.x, zB.y, cB.x, cB.y};

    // j-indexed accumulators; lanes = (even-feature partial, odd-feature partial)
    u64 aA[H], aB[H];
#pragma unroll
    for (int j = 0; j < H; j++) { aA[j] = 0ULL; aB[j] = 0ULL; }

    const ulonglong2* w1T2 = reinterpret_cast<const ulonglong2*>(sW1T);

    // acc[j] += lanes of (v_{2m}, v_{2m+1}) * (W1[2m][j], W1[2m+1][j])
#define ACCM(m, pvA, pvB)                                             \
    {                                                                 \
        const ulonglong2* wr = w1T2 + (m) * 8;                        \
        _Pragma("unroll")                                             \
        for (int q = 0; q < 8; q++) {                                 \
            ulonglong2 wv = wr[q];                                    \
            aA[2 * q]     = fma2((pvA), wv.x, aA[2 * q]);             \
            aA[2 * q + 1] = fma2((pvA), wv.y, aA[2 * q + 1]);         \
            aB[2 * q]     = fma2((pvB), wv.x, aB[2 * q]);             \
            aB[2 * q + 1] = fma2((pvB), wv.y, aB[2 * q + 1]);         \
        }                                                             \
    }

    // raw x features: pairs (x0,x1) at m=0, (x2,x3) at m=1
    {
        u64 pA01 = pack2(xA[0], xA[1]), pB01 = pack2(xB[0], xB[1]);
        u64 pA23 = pack2(xA[2], xA[3]), pB23 = pack2(xB[2], xB[3]);
        ACCM(0, pA01, pB01);
        ACCM(1, pA23, pB23);
    }

    // positional encoding: anchors f=0,5,10 (sincosf), 4 packed doublings each.
    // feature pair index for f: mf = 2 + 4f, pairs = (s0,s1),(s2,s3),(c0,c1),(c2,c3)
#pragma unroll 1
    for (int an = 0; an < 3; an++) {
        const float sc = (an == 0) ? 1.0f : ((an == 1) ? 32.0f : 1024.0f);
        float sa[4], ca[4], sb[4], cb[4];
#pragma unroll
        for (int d = 0; d < 4; d++) {
            sincosf(xA[d] * sc, &sa[d], &ca[d]);
            sincosf(xB[d] * sc, &sb[d], &cb[d]);
        }
        // pack doubling state once; stays packed through the recurrence
        u64 S01A = pack2(sa[0], sa[1]), S23A = pack2(sa[2], sa[3]);
        u64 C01A = pack2(ca[0], ca[1]), C23A = pack2(ca[2], ca[3]);
        u64 S01B = pack2(sb[0], sb[1]), S23B = pack2(sb[2], sb[3]);
        u64 C01B = pack2(cb[0], cb[1]), C23B = pack2(cb[2], cb[3]);
#pragma unroll
        for (int g = 0; g < 5; g++) {
            const int mf = 2 + 4 * (5 * an + g);
            ACCM(mf + 0, S01A, S01B);
            ACCM(mf + 1, S23A, S23B);
            ACCM(mf + 2, C01A, C01B);
            ACCM(mf + 3, C23A, C23B);
            if (g < 4) {   // packed double-angle: S'=2SC, C'=C^2-S^2
                u64 T01A = mul2(S01A, C01A), T23A = mul2(S23A, C23A);
                C01A = fma2(C01A, C01A, neg2(mul2(S01A, S01A)));
                C23A = fma2(C23A, C23A, neg2(mul2(S23A, S23A)));
                S01A = add2(T01A, T01A);  S23A = add2(T23A, T23A);
                u64 T01B = mul2(S01B, C01B), T23B = mul2(S23B, C23B);
                C01B = fma2(C01B, C01B, neg2(mul2(S01B, S01B)));
                C23B = fma2(C23B, C23B, neg2(mul2(S23B, S23B)));
                S01B = add2(T01B, T01B);  S23B = add2(T23B, T23B);
            }
        }
    }

    // first-layer epilogue: lane-sum + bias, leaky -> packed hidden state
    // hp[jp] = (h_{2jp}, h_{2jp+1})  == next layer's multiplier pairs
    u64 hpA[8], hpB[8];
    {
        const u64* bp1 = (const u64*)sB1;
#pragma unroll
        for (int jp = 0; jp < 8; jp++) {
            u64 b = bp1[jp];
            float e0, o0, e1, o1;
            unpack2(aA[2 * jp], e0, o0); unpack2(aA[2 * jp + 1], e1, o1);
            hpA[jp] = leaky2(add2(add2(pack2(e0, e1), pack2(o0, o1)), b));
            unpack2(aB[2 * jp], e0, o0); unpack2(aB[2 * jp + 1], e1, o1);
            hpB[jp] = leaky2(add2(add2(pack2(e0, e1), pack2(o0, o1)), b));
        }
    }

    // ---- 32 residual layers: multiplier = hp[m] directly (no splats) ----
#pragma unroll 2
    for (int L = 0; L < N_LAYERS; L++) {
        const ulonglong2* wT = reinterpret_cast<const ulonglong2*>(sWsT + L * 256);
        const u64* bp = (const u64*)(sBs + L * H);
        u64 tA[H], tB[H];
#pragma unroll
        for (int j = 0; j < H; j++) { tA[j] = 0ULL; tB[j] = 0ULL; }
#pragma unroll
        for (int m = 0; m < 8; m++) {
            const u64 vA = hpA[m];   // already-packed (h_2m, h_2m+1)
            const u64 vB = hpB[m];
#pragma unroll
            for (int q = 0; q < 8; q++) {
                ulonglong2 wv = wT[m * 8 + q];
                tA[2 * q]     = fma2(vA, wv.x, tA[2 * q]);
                tA[2 * q + 1] = fma2(vA, wv.y, tA[2 * q + 1]);
                tB[2 * q]     = fma2(vB, wv.x, tB[2 * q]);
                tB[2 * q + 1] = fma2(vB, wv.y, tB[2 * q + 1]);
            }
        }
        // epilogue: t_j = even+odd partials + b_j; hp += leaky(t) (stays packed)
#pragma unroll
        for (int jp = 0; jp < 8; jp++) {
            u64 b = bp[jp];
            float e0, o0, e1, o1;
            unpack2(tA[2 * jp], e0, o0); unpack2(tA[2 * jp + 1], e1, o1);
            hpA[jp] = resleaky2(add2(add2(pack2(e0, e1), pack2(o0, o1)), b), hpA[jp]);
            unpack2(tB[2 * jp], e0, o0); unpack2(tB[2 * jp + 1], e1, o1);
            hpB[jp] = resleaky2(add2(add2(pack2(e0, e1), pack2(o0, o1)), b), hpB[jp]);
        }
    }

    // ---- Final: out = h @ Wf + bf (packed dot, lane-sum at the end) ----
    const u64* wf2 = (const u64*)sWf;
    u64 oA2 = 0ULL, oB2 = 0ULL;
#pragma unroll
    for (int jp = 0; jp < 8; jp++) {
        u64 w = wf2[jp];
        oA2 = fma2(hpA[jp], w, oA2);
        oB2 = fma2(hpB[jp], w, oB2);
    }
    float a0, a1, b0, b1_;
    unpack2(oA2, a0, a1);
    unpack2(oB2, b0, b1_);
    if (rowA < B) out[rowA] = a0 + a1 + sBf;
    if (rowB < B) out[rowB] = b0 + b1_ + sBf;
}

extern "C" void kernel_launch(void* const* d_in, const int* in_sizes, int n_in,
                              void* d_out, int out_size)
{
    const float* z  = (const float*)d_in[0];
    const float* c  = (const float*)d_in[1];
    const float* W1 = (const float*)d_in[2];
    const float* b1 = (const float*)d_in[3];
    const float* Ws = (const float*)d_in[4];
    const float* bs = (const float*)d_in[5];
    const float* Wf = (const float*)d_in[6];
    const float* bf = (const float*)d_in[7];

    const int B = in_sizes[0] / 2;   // z is (B, 2)
    const int rows_per_block = THREADS * ROWS;
    const int blocks = (B + rows_per_block - 1) / rows_per_block;

    fractal_mlp_kernel<<<blocks, THREADS>>>(z, c, W1, b1, Ws, bs, Wf, bf,
                                            (float*)d_out, B);
}

// round 14
// speedup vs baseline: 1.1626x; 1.0032x over previous
#include <cuda_runtime.h>

typedef unsigned long long u64;

#define POS_DIM 15
#define N_LAYERS 32
#define H 16
#define IN_DIM (4 + 4 * 2 * POS_DIM)   // 124
#define THREADS 192
#define MINCTA 2                        // 2 CTAs/SM -> 12 warps/SM, 170-reg cap
#define ROWS 4                          // rows per thread

#define W1_N (IN_DIM * H)        // 1984
#define WS_N (N_LAYERS * H * H)  // 8192
#define BS_N (N_LAYERS * H)      // 512

// ---- packed f32x2 helpers ----
__device__ __forceinline__ u64 pack2(float lo, float hi) {
    u64 r; asm("mov.b64 %0, {%1, %2};" : "=l"(r) : "f"(lo), "f"(hi)); return r;
}
__device__ __forceinline__ void unpack2(u64 v, float& lo, float& hi) {
    asm("mov.b64 {%0, %1}, %2;" : "=f"(lo), "=f"(hi) : "l"(v));
}
__device__ __forceinline__ u64 fma2(u64 a, u64 b, u64 c) {
    u64 d; asm("fma.rn.f32x2 %0, %1, %2, %3;" : "=l"(d) : "l"(a), "l"(b), "l"(c)); return d;
}
__device__ __forceinline__ u64 mul2(u64 a, u64 b) {
    u64 d; asm("mul.rn.f32x2 %0, %1, %2;" : "=l"(d) : "l"(a), "l"(b)); return d;
}
__device__ __forceinline__ u64 abs2(u64 a) { return a & 0x7fffffff7fffffffULL; }

// leaky(x) = 0.6x + 0.4|x|  (exact for slope 0.2)
#define C06 0x3F19999A3F19999AULL
#define C04 0x3ECCCCCD3ECCCCCDULL

__device__ __forceinline__ u64 resleaky2(u64 t, u64 h_old) {
    return fma2(abs2(t), C04, fma2(t, C06, h_old));
}
__device__ __forceinline__ u64 leaky2(u64 t) {
    return fma2(abs2(t), C04, mul2(t, C06));
}

__global__ __launch_bounds__(THREADS, MINCTA)
void fractal_mlp_kernel(const float* __restrict__ z,
                        const float* __restrict__ c,
                        const float* __restrict__ W1,
                        const float* __restrict__ b1,
                        const float* __restrict__ Ws,
                        const float* __restrict__ bs,
                        const float* __restrict__ Wf,
                        const float* __restrict__ bf,
                        float* __restrict__ out,
                        int B)
{
    __shared__ __align__(16) float sW1[W1_N];
    __shared__ __align__(16) float sWs[WS_N];
    __shared__ __align__(16) float sBs[BS_N];
    __shared__ __align__(16) float sB1[H];
    __shared__ __align__(16) float sWf[H];
    __shared__ float sBf;

    const int tid = threadIdx.x;
    {   // vectorized staging
        const float4* g; float4* s;
        g = (const float4*)W1; s = (float4*)sW1;
        for (int i = tid; i < W1_N / 4; i += THREADS) s[i] = g[i];
        g = (const float4*)Ws; s = (float4*)sWs;
        for (int i = tid; i < WS_N / 4; i += THREADS) s[i] = g[i];
        g = (const float4*)bs; s = (float4*)sBs;
        for (int i = tid; i < BS_N / 4; i += THREADS) s[i] = g[i];
        if (tid < H) { sB1[tid] = b1[tid]; sWf[tid] = Wf[tid]; }
        if (tid == 0) sBf = bf[0];
    }
    __syncthreads();

    const int base = blockIdx.x * (THREADS * ROWS) + tid;
    int row[ROWS], rr[ROWS];
#pragma unroll
    for (int r = 0; r < ROWS; r++) {
        row[r] = base + r * THREADS;
        rr[r] = row[r] < B ? row[r] : B - 1;
    }

    const float2* z2 = reinterpret_cast<const float2*>(z);
    const float2* c2 = reinterpret_cast<const float2*>(c);
    float x[ROWS][4];
#pragma unroll
    for (int r = 0; r < ROWS; r++) {
        float2 zt = z2[rr[r]], ct = c2[rr[r]];
        x[r][0] = zt.x; x[r][1] = zt.y; x[r][2] = ct.x; x[r][3] = ct.y;
    }

    // ---- First layer: acc = b1 + encoded(x) @ W1 (packed over output j pairs) ----
    u64 acc[ROWS][8];
    {
        const ulonglong2* b1v = reinterpret_cast<const ulonglong2*>(sB1);
#pragma unroll
        for (int q = 0; q < 4; q++) {
            ulonglong2 t = b1v[q];
#pragma unroll
            for (int r = 0; r < ROWS; r++) {
                acc[r][2 * q] = t.x; acc[r][2 * q + 1] = t.y;
            }
        }
    }

    const ulonglong2* w1v = reinterpret_cast<const ulonglong2*>(sW1);

    // acc[r] += v[r] * W1[feat, :]  — weights loaded once, reused by all rows
#define ACCR(feat, varr)                                                   \
    {                                                                      \
        u64 pv[ROWS];                                                      \
        _Pragma("unroll")                                                  \
        for (int r = 0; r < ROWS; r++) pv[r] = pack2((varr)[r], (varr)[r]);\
        const ulonglong2* wr = w1v + (feat) * 4;                           \
        _Pragma("unroll")                                                  \
        for (int q = 0; q < 4; q++) {                                      \
            ulonglong2 wv = wr[q];                                         \
            _Pragma("unroll")                                              \
            for (int r = 0; r < ROWS; r++) {                               \
                acc[r][2 * q]     = fma2(pv[r], wv.x, acc[r][2 * q]);      \
                acc[r][2 * q + 1] = fma2(pv[r], wv.y, acc[r][2 * q + 1]);  \
            }                                                              \
        }                                                                  \
    }

#pragma unroll
    for (int d = 0; d < 4; d++) {
        float v[ROWS];
#pragma unroll
        for (int r = 0; r < ROWS; r++) v[r] = x[r][d];
        ACCR(d, v);
    }

    // positional encoding: anchored double-angle (anchors f=0,5,10; 4 doublings each)
#pragma unroll 1
    for (int d = 0; d < 4; d++) {
#pragma unroll
        for (int an = 0; an < 3; an++) {
            const float sc = (an == 0) ? 1.0f : ((an == 1) ? 32.0f : 1024.0f);
            float sv[ROWS], cv[ROWS];
#pragma unroll
            for (int r = 0; r < ROWS; r++)
                sincosf(x[r][d] * sc, &sv[r], &cv[r]);
#pragma unroll
            for (int g = 0; g < 5; g++) {
                const int f = an * 5 + g;
                ACCR(4 + f * 8 + d, sv);   // sin feature
                ACCR(8 + f * 8 + d, cv);   // cos feature
                if (g < 4) {
#pragma unroll
                    for (int r = 0; r < ROWS; r++) {
                        float t = sv[r] * cv[r];
                        float n = fmaf(cv[r], cv[r], -(sv[r] * sv[r]));
                        sv[r] = t + t; cv[r] = n;
                    }
                }
            }
        }
    }

    // first-layer leaky -> scalar h
    float h[ROWS][H];
#pragma unroll
    for (int r = 0; r < ROWS; r++)
#pragma unroll
        for (int p = 0; p < 8; p++)
            unpack2(leaky2(acc[r][p]), h[r][2 * p], h[r][2 * p + 1]);

    // ---- 32 residual layers: h += leaky(h @ W + b) ----
#pragma unroll 2
    for (int L = 0; L < N_LAYERS; L++) {
        const ulonglong2* w = reinterpret_cast<const ulonglong2*>(sWs + L * H * H);
        const ulonglong2* bb = reinterpret_cast<const ulonglong2*>(sBs + L * H);
        u64 a[ROWS][8];
#pragma unroll
        for (int q = 0; q < 4; q++) {
            ulonglong2 t = bb[q];
#pragma unroll
            for (int r = 0; r < ROWS; r++) {
                a[r][2 * q] = t.x; a[r][2 * q + 1] = t.y;
            }
        }
#pragma unroll
        for (int k = 0; k < H; k++) {
            u64 pv[ROWS];
#pragma unroll
            for (int r = 0; r < ROWS; r++) pv[r] = pack2(h[r][k], h[r][k]);
#pragma unroll
            for (int q = 0; q < 4; q++) {
                ulonglong2 wv = w[k * 4 + q];
#pragma unroll
                for (int r = 0; r < ROWS; r++) {
                    a[r][2 * q]     = fma2(pv[r], wv.x, a[r][2 * q]);
                    a[r][2 * q + 1] = fma2(pv[r], wv.y, a[r][2 * q + 1]);
                }
            }
        }
        // fused residual+leaky: h' = h + 0.6t + 0.4|t|
#pragma unroll
        for (int r = 0; r < ROWS; r++)
#pragma unroll
            for (int p = 0; p < 8; p++) {
                u64 hp = pack2(h[r][2 * p], h[r][2 * p + 1]);
                unpack2(resleaky2(a[r][p], hp), h[r][2 * p], h[r][2 * p + 1]);
            }
    }

    // ---- Final: out = h @ Wf + bf ----
#pragma unroll
    for (int r = 0; r < ROWS; r++) {
        float o = sBf;
#pragma unroll
        for (int j = 0; j < H; j++) o = fmaf(h[r][j], sWf[j], o);
        if (row[r] < B) out[row[r]] = o;
    }
}

extern "C" void kernel_launch(void* const* d_in, const int* in_sizes, int n_in,
                              void* d_out, int out_size)
{
    const float* z  = (const float*)d_in[0];
    const float* c  = (const float*)d_in[1];
    const float* W1 = (const float*)d_in[2];
    const float* b1 = (const float*)d_in[3];
    const float* Ws = (const float*)d_in[4];
    const float* bs = (const float*)d_in[5];
    const float* Wf = (const float*)d_in[6];
    const float* bf = (const float*)d_in[7];

    const int B = in_sizes[0] / 2;   // z is (B, 2)
    const int rows_per_block = THREADS * ROWS;
    const int blocks = (B + rows_per_block - 1) / rows_per_block;

    fractal_mlp_kernel<<<blocks, THREADS>>>(z, c, W1, b1, Ws, bs, Wf, bf,
                                            (float*)d_out, B);
}